// round 1
// baseline (speedup 1.0000x reference)
#include <cuda_runtime.h>
#include <cstdint>

// out = x + exp(0.5*(relu(x@W1+b1)@W2 + b2)) * eps
// Shapes: x,eps,out [B,256]; W1 [256,64]; b1 [64]; W2 [64,256]; b2 [256]
// B = 131072 (assumed divisible by 128)

#define SDIM 256
#define HDIM 64
#define TILE_ROWS 128
#define SX_STRIDE 260   // 128*260 floats, bank(addr)=(4r+k)%32
#define SH_STRIDE 68    // bank(addr)=(4r+k)%32

// dynamic smem layout (floats):
//   [0, 128*260)              : sX  (phase A)   / sH [128*68] (phase B, aliased)
//   [128*260, +16384)         : sW1 (phase A)   / sW2 (phase B, aliased)
//   [.., +64)                 : sb1
//   [.., +256)                : sb2
#define SMEM_W_OFF   (TILE_ROWS * SX_STRIDE)
#define SMEM_B1_OFF  (SMEM_W_OFF + SDIM * HDIM)
#define SMEM_B2_OFF  (SMEM_B1_OFF + HDIM)
#define SMEM_FLOATS  (SMEM_B2_OFF + SDIM)
#define SMEM_BYTES   (SMEM_FLOATS * 4)

__global__ void __launch_bounds__(256, 1) mvn_fused_kernel(
    const float* __restrict__ x,
    const float* __restrict__ eps,
    const float* __restrict__ W1,
    const float* __restrict__ b1,
    const float* __restrict__ W2,
    const float* __restrict__ b2,
    float* __restrict__ out)
{
    extern __shared__ float smem[];
    float* sX  = smem;
    float* sW1 = smem + SMEM_W_OFF;
    float* sH  = smem;              // aliases sX after phase A
    float* sW2 = smem + SMEM_W_OFF; // aliases sW1 after phase A
    float* sb1 = smem + SMEM_B1_OFF;
    float* sb2 = smem + SMEM_B2_OFF;

    const int tid = threadIdx.x;
    const int cg  = tid & 15;   // colgroup: 4 consecutive cols
    const int rg  = tid >> 4;   // rowgroup: rows rg + 16*i, i in [0,8)

    const long long rowBase = (long long)blockIdx.x * TILE_ROWS;
    const float* xTile = x + rowBase * SDIM;

    // ---- cooperative loads: X tile, W1, b1, b2 ----
    {
        // X tile: 128*256 floats = 8192 float4
        const float4* src = reinterpret_cast<const float4*>(xTile);
        #pragma unroll
        for (int p = 0; p < 32; p++) {
            int f = tid + 256 * p;          // float4 index
            int r  = f >> 6;                // row
            int kk = f & 63;                // float4 within row
            float4 v = src[f];
            *reinterpret_cast<float4*>(&sX[r * SX_STRIDE + 4 * kk]) = v;
        }
        // W1: 16384 floats = 4096 float4 (dense [256][64])
        const float4* w1s = reinterpret_cast<const float4*>(W1);
        float4* w1d = reinterpret_cast<float4*>(sW1);
        #pragma unroll
        for (int p = 0; p < 16; p++) w1d[tid + 256 * p] = w1s[tid + 256 * p];
        if (tid < 16)
            reinterpret_cast<float4*>(sb1)[tid] = reinterpret_cast<const float4*>(b1)[tid];
        if (tid < 64)
            reinterpret_cast<float4*>(sb2)[tid] = reinterpret_cast<const float4*>(b2)[tid];
    }
    __syncthreads();

    // ---- Phase A: H = relu(X @ W1 + b1), thread computes 8 rows x 4 cols ----
    float acc[8][4];
    #pragma unroll
    for (int i = 0; i < 8; i++)
        #pragma unroll
        for (int j = 0; j < 4; j++) acc[i][j] = 0.0f;

    #pragma unroll 2
    for (int k = 0; k < SDIM; k++) {
        float4 b = *reinterpret_cast<const float4*>(&sW1[k * HDIM + 4 * cg]);
        float a[8];
        #pragma unroll
        for (int i = 0; i < 8; i++) a[i] = sX[(rg + 16 * i) * SX_STRIDE + k];
        #pragma unroll
        for (int i = 0; i < 8; i++) {
            acc[i][0] += a[i] * b.x;
            acc[i][1] += a[i] * b.y;
            acc[i][2] += a[i] * b.z;
            acc[i][3] += a[i] * b.w;
        }
    }

    float4 bb1 = *reinterpret_cast<const float4*>(&sb1[4 * cg]);

    __syncthreads();  // everyone done reading sX / sW1

    // write H (relu + bias) into sH; cooperatively load W2 into sW2
    #pragma unroll
    for (int i = 0; i < 8; i++) {
        float4 hv;
        hv.x = fmaxf(acc[i][0] + bb1.x, 0.0f);
        hv.y = fmaxf(acc[i][1] + bb1.y, 0.0f);
        hv.z = fmaxf(acc[i][2] + bb1.z, 0.0f);
        hv.w = fmaxf(acc[i][3] + bb1.w, 0.0f);
        *reinterpret_cast<float4*>(&sH[(rg + 16 * i) * SH_STRIDE + 4 * cg]) = hv;
    }
    {
        const float4* w2s = reinterpret_cast<const float4*>(W2);
        float4* w2d = reinterpret_cast<float4*>(sW2);
        #pragma unroll
        for (int p = 0; p < 16; p++) w2d[tid + 256 * p] = w2s[tid + 256 * p];
    }
    __syncthreads();

    // ---- Phase B: logits = H @ W2 + b2; out = x + exp(0.5*logit)*eps ----
    const float* epsTile = eps + rowBase * SDIM;
    float* outTile = out + rowBase * SDIM;

    #pragma unroll
    for (int c = 0; c < 4; c++) {
        float acc2[8][4];
        #pragma unroll
        for (int i = 0; i < 8; i++)
            #pragma unroll
            for (int j = 0; j < 4; j++) acc2[i][j] = 0.0f;

        #pragma unroll 2
        for (int k = 0; k < HDIM; k++) {
            float4 b = *reinterpret_cast<const float4*>(&sW2[k * SDIM + c * 64 + 4 * cg]);
            float a[8];
            #pragma unroll
            for (int i = 0; i < 8; i++) a[i] = sH[(rg + 16 * i) * SH_STRIDE + k];
            #pragma unroll
            for (int i = 0; i < 8; i++) {
                acc2[i][0] += a[i] * b.x;
                acc2[i][1] += a[i] * b.y;
                acc2[i][2] += a[i] * b.z;
                acc2[i][3] += a[i] * b.w;
            }
        }

        float4 bb2 = *reinterpret_cast<const float4*>(&sb2[c * 64 + 4 * cg]);

        #pragma unroll
        for (int i = 0; i < 8; i++) {
            int r = rg + 16 * i;
            long long idx = (long long)r * SDIM + c * 64 + 4 * cg;
            float4 xv = *reinterpret_cast<const float4*>(&xTile[idx]);
            float4 ev = *reinterpret_cast<const float4*>(&epsTile[idx]);
            float4 o;
            o.x = fmaf(__expf(0.5f * (acc2[i][0] + bb2.x)), ev.x, xv.x);
            o.y = fmaf(__expf(0.5f * (acc2[i][1] + bb2.y)), ev.y, xv.y);
            o.z = fmaf(__expf(0.5f * (acc2[i][2] + bb2.z)), ev.z, xv.z);
            o.w = fmaf(__expf(0.5f * (acc2[i][3] + bb2.w)), ev.w, xv.w);
            *reinterpret_cast<float4*>(&outTile[idx]) = o;
        }
    }
}

extern "C" void kernel_launch(void* const* d_in, const int* in_sizes, int n_in,
                              void* d_out, int out_size) {
    const float* x   = (const float*)d_in[0];
    const float* eps = (const float*)d_in[1];
    const float* W1  = (const float*)d_in[2];
    const float* b1  = (const float*)d_in[3];
    const float* W2  = (const float*)d_in[4];
    const float* b2  = (const float*)d_in[5];
    float* out = (float*)d_out;

    int B = in_sizes[0] / SDIM;
    int grid = B / TILE_ROWS;  // 1024 for B=131072

    static bool attr_set = false;  // idempotent attribute, deterministic work
    if (!attr_set) {
        cudaFuncSetAttribute(mvn_fused_kernel,
                             cudaFuncAttributeMaxDynamicSharedMemorySize, SMEM_BYTES);
        attr_set = true;
    }

    mvn_fused_kernel<<<grid, 256, SMEM_BYTES>>>(x, eps, W1, b1, W2, b2, out);
}